// round 2
// baseline (speedup 1.0000x reference)
#include <cuda_runtime.h>
#include <cstddef>

// Linear recurrence scan: c_t = a_t * c_{t-1} + b_t   (c_{-1} = 0)
// input  : [B, T, 2*UNITS]  (a = [:, :, :UNITS], b = [:, :, UNITS:])
// output : [B, T, UNITS]
//
// One thread per (batch, unit) sequence; coalesced 128B transactions.
// R2: unroll/prefetch depth 8 -> 16 (4MB chip-wide outstanding loads, vs 2MB
// at R1 which capped DRAM at 63.5%), and block 256 -> 128 so the 256 blocks
// cover all 148 SMs (R1's 128 blocks left 20 SMs idle).

#ifndef UNITS_C
#define UNITS_C 2048
#endif
#ifndef T_C
#define T_C 2048
#endif

__global__ void __launch_bounds__(128, 1)
tempo_scan_kernel(const float* __restrict__ in, float* __restrict__ out)
{
    constexpr int UNITS = UNITS_C;
    constexpr int T     = T_C;
    constexpr int ROW   = 2 * UNITS;   // input row stride in elements
    constexpr int U     = 16;          // time unroll / prefetch depth

    const int tid = blockIdx.x * blockDim.x + threadIdx.x;
    const int g   = tid >> 11;         // batch index   (tid / UNITS)
    const int u   = tid & (UNITS - 1); // unit index

    const float* pa = in  + (size_t)g * T * ROW   + u;          // a[g, t, u]
    const float* pb = pa + UNITS;                                // b[g, t, u]
    float*       po = out + (size_t)g * T * UNITS + u;           // c[g, t, u]

    float a_cur[U], b_cur[U];

    // Prologue: prefetch block 0 (streaming loads; zero reuse)
    #pragma unroll
    for (int i = 0; i < U; ++i) {
        a_cur[i] = __ldcs(pa + (size_t)i * ROW);
        b_cur[i] = __ldcs(pb + (size_t)i * ROW);
    }

    float c = 0.0f;

    for (int t = 0; t < T; t += U) {
        float a_nxt[U], b_nxt[U];
        const int tn = t + U;
        if (tn < T) {
            // Prefetch next time-block: 32 independent LDGs in flight per
            // thread while the dependent FMA chain drains the current block.
            #pragma unroll
            for (int i = 0; i < U; ++i) {
                a_nxt[i] = __ldcs(pa + (size_t)(tn + i) * ROW);
                b_nxt[i] = __ldcs(pb + (size_t)(tn + i) * ROW);
            }
        }

        // Serial recurrence over the current block + streaming stores.
        #pragma unroll
        for (int i = 0; i < U; ++i) {
            c = fmaf(a_cur[i], c, b_cur[i]);
            __stcs(po + (size_t)(t + i) * UNITS, c);
        }

        #pragma unroll
        for (int i = 0; i < U; ++i) {
            a_cur[i] = a_nxt[i];
            b_cur[i] = b_nxt[i];
        }
    }
}

extern "C" void kernel_launch(void* const* d_in, const int* in_sizes, int n_in,
                              void* d_out, int out_size)
{
    const float* in  = (const float*)d_in[0];
    float*       out = (float*)d_out;

    const int batch    = in_sizes[0] / (T_C * 2 * UNITS_C);
    const int nthreads = batch * UNITS_C;          // one thread per sequence
    const int block    = 128;
    const int grid     = (nthreads + block - 1) / block;   // 256 for B=16

    tempo_scan_kernel<<<grid, block>>>(in, out);
}

// round 3
// speedup vs baseline: 1.2158x; 1.2158x over previous
#include <cuda_runtime.h>
#include <cstddef>
#include <cstdint>

// Single-pass decoupled-chaining scan for c_t = a_t * c_{t-1} + b_t, c_{-1}=0.
// input  : [B, T, 2*UNITS] fp32   (a = [:,:,:UNITS], b = [:,:,UNITS:])
// output : [B, T, UNITS]
//
// Time axis split into CH=32 chunks of 64 steps -> 8192 blocks / ~2M threads
// (R1/R2 plateaued at 62% DRAM with only 32768 threads). Each block:
//   * 256 threads = 8 time-segments x 32 lanes, one float4 (4 units) per lane
//   * loads its whole tile (16 LDG.128/thread) before any waiting
//   * local scan in registers, segment aggregates combined via smem
//   * waits for predecessor chunk's carry (32 float4) via per-lane
//     release/acquire flags, publishes its own carry before storing outputs.
// Flags are zeroed by a prologue kernel each launch (graph-replay safe).

#define T_C      2048
#define UNITS_C  2048
#define B_MAX    16

constexpr int LANES   = 32;
constexpr int SEGS    = 8;
constexpr int LSEG    = 8;                    // timesteps per thread
constexpr int CHUNK_T = SEGS * LSEG;          // 64
constexpr int CH      = T_C / CHUNK_T;        // 32
constexpr int VG      = UNITS_C / (LANES*4);  // 16 vec-groups per batch row
constexpr int NROWS   = B_MAX * VG * CH;      // 8192 carry rows

__device__ float4   g_prefix[NROWS][LANES];
__device__ unsigned g_flag  [NROWS][LANES];

__global__ void reset_flags_kernel()
{
    int i = blockIdx.x * blockDim.x + threadIdx.x;   // NROWS*LANES = 262144
    ((unsigned*)g_flag)[i] = 0u;
}

__device__ __forceinline__ float4 f4_fma(float4 a, float4 x, float4 b)
{   // a*x + b
    float4 r;
    r.x = fmaf(a.x, x.x, b.x); r.y = fmaf(a.y, x.y, b.y);
    r.z = fmaf(a.z, x.z, b.z); r.w = fmaf(a.w, x.w, b.w);
    return r;
}
__device__ __forceinline__ float4 f4_mul(float4 a, float4 b)
{
    float4 r; r.x=a.x*b.x; r.y=a.y*b.y; r.z=a.z*b.z; r.w=a.w*b.w; return r;
}

__global__ void __launch_bounds__(256, 2)
tempo_scan_kernel(const float* __restrict__ in, float* __restrict__ out, int nbatch)
{
    const int lane = threadIdx.x & 31;
    const int seg  = threadIdx.x >> 5;

    // chunk index in the HIGH bits of blockIdx so chunk-0 blocks dispatch first
    const int gpb = nbatch * VG;
    const int p   = blockIdx.x / gpb;          // time chunk
    const int r   = blockIdx.x % gpb;
    const int g   = r / VG;                    // batch
    const int vg  = r % VG;                    // vec-group (32 float4 lanes)

    const int t0 = p * CHUNK_T + seg * LSEG;
    const size_t uf = (size_t)(vg * LANES + lane) * 4;   // unit offset (floats)

    constexpr int ROW  = 2 * UNITS_C;          // input row stride (floats)
    constexpr int RS4  = ROW / 4;              // float4 stride: 1024
    constexpr int OS4  = UNITS_C / 4;          // 512

    const float4* pa = (const float4*)(in + ((size_t)g * T_C + t0) * ROW + uf);
    const float4* pb = (const float4*)(in + ((size_t)g * T_C + t0) * ROW + UNITS_C + uf);
    float4*       po = (float4*)(out + ((size_t)g * T_C + t0) * UNITS_C + uf);

    // ---- phase 1: issue all loads immediately (this is ALL the HBM read) ----
    float4 A[LSEG], C[LSEG];
    #pragma unroll
    for (int i = 0; i < LSEG; ++i) {
        A[i] = __ldcs(pa + (size_t)i * RS4);
        C[i] = __ldcs(pb + (size_t)i * RS4);
    }

    // local scan with zero prefix: C[i] = c_local_i, A[i] = prod_{j<=i} a_j
    #pragma unroll
    for (int i = 1; i < LSEG; ++i) {
        C[i] = f4_fma(A[i], C[i-1], C[i]);
        A[i] = f4_mul(A[i], A[i-1]);
    }

    // ---- intra-block segment scan via smem ----
    __shared__ float4 sA[SEGS][LANES];
    __shared__ float4 sC[SEGS][LANES];
    __shared__ float4 sP[LANES];

    sA[seg][lane] = A[LSEG-1];
    sC[seg][lane] = C[LSEG-1];
    __syncthreads();

    // exclusive prefix over segments 0..seg-1:  E = (EA, EC)
    float4 EA = make_float4(1.f,1.f,1.f,1.f);
    float4 EC = make_float4(0.f,0.f,0.f,0.f);
    #pragma unroll
    for (int j = 0; j < SEGS-1; ++j) {
        if (j < seg) {
            float4 Aj = sA[j][lane], Cj = sC[j][lane];
            EC = f4_fma(Aj, EC, Cj);     // apply segment j after current prefix
            EA = f4_mul(Aj, EA);
        }
    }

    // ---- fetch predecessor chunk's carry (warp 0), broadcast via smem ----
    if (seg == 0) {
        float4 P = make_float4(0.f,0.f,0.f,0.f);
        if (p > 0) {
            const int rprev = ((p-1) * nbatch + g) * VG + vg;
            const unsigned* f = &g_flag[rprev][lane];
            unsigned v;
            asm volatile("ld.global.acquire.gpu.b32 %0, [%1];"
                         : "=r"(v) : "l"(f) : "memory");
            while (!v) {
                __nanosleep(40);
                asm volatile("ld.global.acquire.gpu.b32 %0, [%1];"
                             : "=r"(v) : "l"(f) : "memory");
            }
            P = g_prefix[rprev][lane];
        }
        sP[lane] = P;
    }
    __syncthreads();

    // full c-prefix at this thread's segment start
    const float4 P  = sP[lane];
    const float4 Pc = f4_fma(EA, P, EC);

    // ---- publish own carry FIRST (shortens the cross-chunk chain) ----
    if (seg == SEGS-1 && p < CH-1) {
        const int rcur = (p * nbatch + g) * VG + vg;
        float4 carry = f4_fma(A[LSEG-1], Pc, C[LSEG-1]);
        g_prefix[rcur][lane] = carry;
        asm volatile("st.global.release.gpu.b32 [%0], %1;"
                     :: "l"(&g_flag[rcur][lane]), "r"(1u) : "memory");
    }

    // ---- finalize + store outputs ----
    #pragma unroll
    for (int i = 0; i < LSEG; ++i) {
        float4 cf = f4_fma(A[i], Pc, C[i]);
        __stcs(po + (size_t)i * OS4, cf);
    }
}

extern "C" void kernel_launch(void* const* d_in, const int* in_sizes, int n_in,
                              void* d_out, int out_size)
{
    const float* in  = (const float*)d_in[0];
    float*       out = (float*)d_out;

    const int batch = in_sizes[0] / (T_C * 2 * UNITS_C);

    reset_flags_kernel<<<(NROWS * LANES) / 256, 256>>>();

    const int grid = CH * batch * VG;      // 8192 for B=16
    tempo_scan_kernel<<<grid, 256>>>(in, out, batch);
}